// round 1
// baseline (speedup 1.0000x reference)
#include <cuda_runtime.h>
#include <cstddef>

// Problem constants
#define SQ   1024          // sequence length S
#define BB   8             // batch B
#define EE   1024          // embed E
#define HH   16            // heads
#define DD   64            // head dim
#define DFF  4096
#define MTOK (SQ * BB)     // 8192 token rows
#define E3   (3 * EE)      // 3072

// ---------------------------------------------------------------------------
// Scratch (no allocations allowed -> __device__ globals)
// ---------------------------------------------------------------------------
__device__ float g_qkv[(size_t)MTOK * E3];     // 96 MB
__device__ float g_ctx[(size_t)MTOK * EE];     // 32 MB
__device__ float g_tmp[(size_t)MTOK * EE];     // attn_out, later ff2_out
__device__ float g_x  [(size_t)MTOK * EE];     // ln1 output
__device__ float g_ff1[(size_t)MTOK * DFF];    // 128 MB

// ---------------------------------------------------------------------------
// GEMM: C[M,N] = A[M,K] @ B[N,K]^T + bias[N]   (both A and B row-major, K inner)
// EPI: 0 = bias, 1 = bias + relu
// Tiles: 128x128, BK=8, 256 threads, 8x8 per-thread micro-tile.
// M, N multiples of 128; K multiple of 8 (and of 4 for float4 loads).
// ---------------------------------------------------------------------------
template <int EPI>
__global__ __launch_bounds__(256, 2)
void gemm_kernel(const float* __restrict__ A, const float* __restrict__ Bm,
                 const float* __restrict__ bias, float* __restrict__ C,
                 int Mdim, int Ndim, int Kdim)
{
    __shared__ float As[8][128];
    __shared__ float Bs[8][128];

    const int bm = blockIdx.y * 128;
    const int bn = blockIdx.x * 128;
    const int t  = threadIdx.x;
    const int tx = t & 15;        // 0..15  -> N micro
    const int ty = t >> 4;        // 0..15  -> M micro

    // loader: thread t covers row lr (0..127), k-quad lc (0 or 4)
    const int lr = t >> 1;
    const int lc = (t & 1) * 4;

    const float* Aptr = A + (size_t)(bm + lr) * Kdim + lc;
    const float* Bptr = Bm + (size_t)(bn + lr) * Kdim + lc;

    float acc[8][8];
#pragma unroll
    for (int i = 0; i < 8; i++)
#pragma unroll
        for (int j = 0; j < 8; j++) acc[i][j] = 0.0f;

    for (int k0 = 0; k0 < Kdim; k0 += 8) {
        float4 a4 = *(const float4*)(Aptr + k0);
        float4 b4 = *(const float4*)(Bptr + k0);
        As[lc + 0][lr] = a4.x; As[lc + 1][lr] = a4.y;
        As[lc + 2][lr] = a4.z; As[lc + 3][lr] = a4.w;
        Bs[lc + 0][lr] = b4.x; Bs[lc + 1][lr] = b4.y;
        Bs[lc + 2][lr] = b4.z; Bs[lc + 3][lr] = b4.w;
        __syncthreads();

#pragma unroll
        for (int kk = 0; kk < 8; kk++) {
            float4 a0 = *(const float4*)&As[kk][ty * 8];
            float4 a1 = *(const float4*)&As[kk][ty * 8 + 4];
            float4 b0 = *(const float4*)&Bs[kk][tx * 8];
            float4 b1 = *(const float4*)&Bs[kk][tx * 8 + 4];
            float ar[8] = {a0.x, a0.y, a0.z, a0.w, a1.x, a1.y, a1.z, a1.w};
            float br[8] = {b0.x, b0.y, b0.z, b0.w, b1.x, b1.y, b1.z, b1.w};
#pragma unroll
            for (int i = 0; i < 8; i++)
#pragma unroll
                for (int j = 0; j < 8; j++)
                    acc[i][j] = fmaf(ar[i], br[j], acc[i][j]);
        }
        __syncthreads();
    }

    float bi[8];
#pragma unroll
    for (int j = 0; j < 8; j++) bi[j] = bias[bn + tx * 8 + j];

#pragma unroll
    for (int i = 0; i < 8; i++) {
        float* Crow = C + (size_t)(bm + ty * 8 + i) * Ndim + bn + tx * 8;
#pragma unroll
        for (int j = 0; j < 8; j++) {
            float v = acc[i][j] + bi[j];
            if (EPI == 1) v = fmaxf(v, 0.0f);
            Crow[j] = v;
        }
    }
}

// ---------------------------------------------------------------------------
// Flash attention, fp32, online softmax.
// grid = B*H*(S/64) blocks, 256 threads.
// Block handles 64 query rows of one head, streams keys in 32-row tiles.
// Thread t: query row r = t>>2, quadrant q = t&3.
//   S compute : thread owns keys  k = q*8 + j   (j 0..7)
//   PV compute: thread owns dims  d = q + dd*4  (dd 0..15)
// ---------------------------------------------------------------------------
__global__ __launch_bounds__(256)
void attn_kernel(const float* __restrict__ qkv, float* __restrict__ ctx)
{
    __shared__ float Qs[64][64];
    __shared__ float Ks[32][65];   // pad 65: 8-row stride -> distinct banks
    __shared__ float Vs[32][64];
    __shared__ float Ps[64][33];

    const int qt = blockIdx.x & 15;       // q tile 0..15
    const int bh = blockIdx.x >> 4;       // 0..127
    const int b  = bh / HH;
    const int h  = bh % HH;

    const int t = threadIdx.x;
    const int r = t >> 2;                 // query row 0..63
    const int q = t & 3;

    const size_t rowstride = (size_t)BB * E3;   // stride between s and s+1
    const float* Qg = qkv + ((size_t)(qt * 64) * BB + b) * E3 + h * DD;
    const float* Kg = qkv + (size_t)b * E3 + EE + h * DD;
    const float* Vg = Kg + EE;

    // load Q tile, pre-scaled by 1/sqrt(D) = 0.125
#pragma unroll
    for (int i = 0; i < 16; i++) {
        int e = t + i * 256;              // 0..4095
        int row = e >> 6, col = e & 63;
        Qs[row][col] = Qg[(size_t)row * rowstride + col] * 0.125f;
    }

    float o[16];
#pragma unroll
    for (int dd = 0; dd < 16; dd++) o[dd] = 0.0f;
    float m_i = -1e30f, l_i = 0.0f;

    __syncthreads();

    for (int kt = 0; kt < SQ / 32; kt++) {
        // load K,V tiles
#pragma unroll
        for (int i = 0; i < 8; i++) {
            int e = t + i * 256;          // 0..2047
            int row = e >> 6, col = e & 63;
            size_t goff = (size_t)(kt * 32 + row) * rowstride + col;
            Ks[row][col] = Kg[goff];
            Vs[row][col] = Vg[goff];
        }
        __syncthreads();

        // S = Q K^T  (thread: 8 keys)
        float sacc[8] = {0, 0, 0, 0, 0, 0, 0, 0};
        const int kb = q * 8;
#pragma unroll 8
        for (int d = 0; d < 64; d++) {
            float qd = Qs[r][d];
#pragma unroll
            for (int j = 0; j < 8; j++)
                sacc[j] = fmaf(qd, Ks[kb + j][d], sacc[j]);
        }

        // online softmax for this row (4 lanes per row, contiguous in warp)
        float tmax = sacc[0];
#pragma unroll
        for (int j = 1; j < 8; j++) tmax = fmaxf(tmax, sacc[j]);
        tmax = fmaxf(tmax, __shfl_xor_sync(0xffffffffu, tmax, 1));
        tmax = fmaxf(tmax, __shfl_xor_sync(0xffffffffu, tmax, 2));

        float new_m = fmaxf(m_i, tmax);
        float corr  = __expf(m_i - new_m);

        float tsum = 0.0f;
        float p[8];
#pragma unroll
        for (int j = 0; j < 8; j++) {
            p[j] = __expf(sacc[j] - new_m);
            tsum += p[j];
        }
        tsum += __shfl_xor_sync(0xffffffffu, tsum, 1);
        tsum += __shfl_xor_sync(0xffffffffu, tsum, 2);

        l_i = l_i * corr + tsum;
        m_i = new_m;
#pragma unroll
        for (int dd = 0; dd < 16; dd++) o[dd] *= corr;
#pragma unroll
        for (int j = 0; j < 8; j++) Ps[r][kb + j] = p[j];
        __syncthreads();

        // O += P @ V   (thread: 16 dims, d = q + dd*4 -> conflict-free Vs)
#pragma unroll 4
        for (int k = 0; k < 32; k++) {
            float pv = Ps[r][k];
#pragma unroll
            for (int dd = 0; dd < 16; dd++)
                o[dd] = fmaf(pv, Vs[k][q + dd * 4], o[dd]);
        }
        __syncthreads();
    }

    float inv_l = 1.0f / l_i;
    const int srow = qt * 64 + r;
    float* Cp = ctx + ((size_t)srow * BB + b) * EE + h * DD;
#pragma unroll
    for (int dd = 0; dd < 16; dd++)
        Cp[q + dd * 4] = o[dd] * inv_l;
}

// ---------------------------------------------------------------------------
// out = layernorm(a + b) * g + beta, one block per row of 1024
// ---------------------------------------------------------------------------
__global__ __launch_bounds__(256)
void add_ln_kernel(const float* __restrict__ a, const float* __restrict__ bres,
                   const float* __restrict__ g, const float* __restrict__ beta,
                   float* __restrict__ out)
{
    const int row = blockIdx.x;
    const int t   = threadIdx.x;
    const float4* A4 = (const float4*)(a    + (size_t)row * EE);
    const float4* B4 = (const float4*)(bres + (size_t)row * EE);

    float4 x = A4[t];
    float4 y = B4[t];
    x.x += y.x; x.y += y.y; x.z += y.z; x.w += y.w;

    float s  = x.x + x.y + x.z + x.w;
    float ss = x.x * x.x + x.y * x.y + x.z * x.z + x.w * x.w;

#pragma unroll
    for (int off = 16; off > 0; off >>= 1) {
        s  += __shfl_xor_sync(0xffffffffu, s,  off);
        ss += __shfl_xor_sync(0xffffffffu, ss, off);
    }
    __shared__ float sh_s[8], sh_ss[8];
    const int w = t >> 5, l = t & 31;
    if (l == 0) { sh_s[w] = s; sh_ss[w] = ss; }
    __syncthreads();
    s = 0.0f; ss = 0.0f;
#pragma unroll
    for (int i = 0; i < 8; i++) { s += sh_s[i]; ss += sh_ss[i]; }

    const float mean = s * (1.0f / EE);
    const float var  = ss * (1.0f / EE) - mean * mean;
    const float rstd = rsqrtf(var + 1e-5f);

    float4 g4 = ((const float4*)g)[t];
    float4 b4 = ((const float4*)beta)[t];
    float4 o;
    o.x = (x.x - mean) * rstd * g4.x + b4.x;
    o.y = (x.y - mean) * rstd * g4.y + b4.y;
    o.z = (x.z - mean) * rstd * g4.z + b4.z;
    o.w = (x.w - mean) * rstd * g4.w + b4.w;
    ((float4*)(out + (size_t)row * EE))[t] = o;
}

// ---------------------------------------------------------------------------
// launch
// ---------------------------------------------------------------------------
extern "C" void kernel_launch(void* const* d_in, const int* in_sizes, int n_in,
                              void* d_out, int out_size)
{
    const float* src    = (const float*)d_in[0];
    const float* in_w   = (const float*)d_in[1];
    const float* in_b   = (const float*)d_in[2];
    const float* out_w  = (const float*)d_in[3];
    const float* out_b  = (const float*)d_in[4];
    const float* ln1g   = (const float*)d_in[5];
    const float* ln1b   = (const float*)d_in[6];
    const float* ln2g   = (const float*)d_in[7];
    const float* ln2b   = (const float*)d_in[8];
    const float* w1     = (const float*)d_in[9];
    const float* b1     = (const float*)d_in[10];
    const float* w2     = (const float*)d_in[11];
    const float* b2     = (const float*)d_in[12];
    float* out = (float*)d_out;

    float *qkv, *ctx, *tmp, *x, *ff1;
    cudaGetSymbolAddress((void**)&qkv, g_qkv);
    cudaGetSymbolAddress((void**)&ctx, g_ctx);
    cudaGetSymbolAddress((void**)&tmp, g_tmp);
    cudaGetSymbolAddress((void**)&x,   g_x);
    cudaGetSymbolAddress((void**)&ff1, g_ff1);

    // 1. qkv = src @ in_proj_w^T + in_proj_b     (8192 x 3072 x 1024)
    gemm_kernel<0><<<dim3(E3 / 128, MTOK / 128), 256>>>(src, in_w, in_b, qkv,
                                                        MTOK, E3, EE);
    // 2. flash attention -> ctx (token-major, (8192,1024))
    attn_kernel<<<BB * HH * (SQ / 64), 256>>>(qkv, ctx);

    // 3. attn_out = ctx @ out_w^T + out_b        (8192 x 1024 x 1024)
    gemm_kernel<0><<<dim3(EE / 128, MTOK / 128), 256>>>(ctx, out_w, out_b, tmp,
                                                        MTOK, EE, EE);
    // 4. x = LN1(src + attn_out)
    add_ln_kernel<<<MTOK, 256>>>(src, tmp, ln1g, ln1b, x);

    // 5. ff1 = relu(x @ w1^T + b1)               (8192 x 4096 x 1024)
    gemm_kernel<1><<<dim3(DFF / 128, MTOK / 128), 256>>>(x, w1, b1, ff1,
                                                         MTOK, DFF, EE);
    // 6. ff2 = ff1 @ w2^T + b2                   (8192 x 1024 x 4096)
    gemm_kernel<0><<<dim3(EE / 128, MTOK / 128), 256>>>(ff1, w2, b2, tmp,
                                                        MTOK, EE, DFF);
    // 7. out = LN2(x + ff2)
    add_ln_kernel<<<MTOK, 256>>>(x, tmp, ln2g, ln2b, out);
}